// round 1
// baseline (speedup 1.0000x reference)
#include <cuda_runtime.h>

// ---------------------------------------------------------------------------
// AttentionHead: q/k/v projections ([B,S,1024] -> [B,S,64]) + softmax attention
// B=4, S=2048, d_model=1024, d_k=d_v=64, fp32 throughout.
// ---------------------------------------------------------------------------

constexpr int DM  = 1024;
constexpr int DK  = 64;
constexpr int SEQ = 2048;
constexpr int NB  = 4;
constexpr int BSR = NB * SEQ;   // 8192 rows

// Intermediate projected Q/K/V (scratch; __device__ globals, no allocation)
__device__ float g_Q[NB * SEQ * DK];
__device__ float g_K[NB * SEQ * DK];
__device__ float g_V[NB * SEQ * DK];

// ---------------------------------------------------------------------------
// Projection: out[r][c] = sum_k X[r][k] * W[k][c] + b[c]
// Tile: 128 rows x 64 cols per block, K-chunk 32, 8x8 register blocking.
// ---------------------------------------------------------------------------
__global__ __launch_bounds__(128)
void proj_kernel(const float* __restrict__ q, const float* __restrict__ k,
                 const float* __restrict__ v,
                 const float* __restrict__ Wq, const float* __restrict__ bq,
                 const float* __restrict__ Wk, const float* __restrict__ bk,
                 const float* __restrict__ Wv, const float* __restrict__ bv)
{
    __shared__ float Xs[32][132];   // transposed X chunk: Xs[k][row], pad for banks+align
    __shared__ float Ws[32][64];    // W chunk: Ws[k][col]

    const int which = blockIdx.y;
    const float* X    = (which == 0) ? q  : (which == 1) ? k  : v;
    const float* W    = (which == 0) ? Wq : (which == 1) ? Wk : Wv;
    const float* bias = (which == 0) ? bq : (which == 1) ? bk : bv;
    float* out        = (which == 0) ? g_Q : (which == 1) ? g_K : g_V;

    const int t  = threadIdx.x;
    const int r0 = blockIdx.x * 128;
    const int rg = t & 15;   // 16 row-groups of 8 rows
    const int cg = t >> 4;   // 8 col-groups of 8 cols

    float acc[8][8];
#pragma unroll
    for (int i = 0; i < 8; i++)
#pragma unroll
        for (int j = 0; j < 8; j++) acc[i][j] = 0.f;

    for (int kk = 0; kk < DM; kk += 32) {
        // stage X chunk transposed: coalesced 128B reads per 8-lane group
#pragma unroll
        for (int p = 0; p < 8; p++) {
            int row = p * 16 + (t >> 3);
            int kq  = (t & 7) * 4;
            float4 xv = *(const float4*)&X[(r0 + row) * DM + kk + kq];
            Xs[kq + 0][row] = xv.x; Xs[kq + 1][row] = xv.y;
            Xs[kq + 2][row] = xv.z; Xs[kq + 3][row] = xv.w;
        }
        // stage W chunk (row-major, fully coalesced float4)
#pragma unroll
        for (int i = 0; i < 4; i++) {
            int f  = i * 128 + t;          // 0..511 float4s
            int kr = f >> 4;
            int c4 = (f & 15) * 4;
            *(float4*)&Ws[kr][c4] = *(const float4*)&W[(kk + kr) * DK + c4];
        }
        __syncthreads();

#pragma unroll 8
        for (int kx = 0; kx < 32; kx++) {
            float4 a0 = *(float4*)&Xs[kx][rg * 8];
            float4 a1 = *(float4*)&Xs[kx][rg * 8 + 4];
            float4 b0 = *(float4*)&Ws[kx][cg * 8];
            float4 b1 = *(float4*)&Ws[kx][cg * 8 + 4];
            float a[8] = {a0.x, a0.y, a0.z, a0.w, a1.x, a1.y, a1.z, a1.w};
            float b[8] = {b0.x, b0.y, b0.z, b0.w, b1.x, b1.y, b1.z, b1.w};
#pragma unroll
            for (int i = 0; i < 8; i++)
#pragma unroll
                for (int j = 0; j < 8; j++) acc[i][j] += a[i] * b[j];
        }
        __syncthreads();
    }

    float bc[8];
#pragma unroll
    for (int j = 0; j < 8; j++) bc[j] = bias[cg * 8 + j];

#pragma unroll
    for (int i = 0; i < 8; i++) {
        int r = r0 + rg * 8 + i;
        float4 o0 = {acc[i][0] + bc[0], acc[i][1] + bc[1],
                     acc[i][2] + bc[2], acc[i][3] + bc[3]};
        float4 o1 = {acc[i][4] + bc[4], acc[i][5] + bc[5],
                     acc[i][6] + bc[6], acc[i][7] + bc[7]};
        *(float4*)&out[r * DK + cg * 8]     = o0;
        *(float4*)&out[r * DK + cg * 8 + 4] = o1;
    }
}

// ---------------------------------------------------------------------------
// Flash attention: q-tile 64, k-tile 64, online softmax.
// ---------------------------------------------------------------------------
struct AttnSmem {
    float Qt[64][68];   // Qt[d][qrow]
    float Kt[64][68];   // Kt[d][kcol]
    float Pt[64][68];   // Pt[kcol][qrow] : raw scores then exp'd P
    float Vs[64][64];   // Vs[kcol][v]
    float m_s[64], l_s[64], fs[64];
    float pm[128], ps[128];
};

__global__ __launch_bounds__(128)
void attn_kernel(float* __restrict__ out)
{
    extern __shared__ char smraw[];
    AttnSmem& sm = *reinterpret_cast<AttnSmem*>(smraw);

    const int t  = threadIdx.x;
    const int q0 = blockIdx.x * 64;
    const int b  = blockIdx.y;
    const int base = b * SEQ;
    const float NEG_INF = __int_as_float(0xff800000u);

    // load Q tile transposed
#pragma unroll
    for (int i = 0; i < 8; i++) {
        int f  = i * 128 + t;     // 0..1023 float4s
        int r  = f >> 4;
        int d4 = (f & 15) * 4;
        float4 qv = *(const float4*)&g_Q[(base + q0 + r) * DK + d4];
        sm.Qt[d4 + 0][r] = qv.x; sm.Qt[d4 + 1][r] = qv.y;
        sm.Qt[d4 + 2][r] = qv.z; sm.Qt[d4 + 3][r] = qv.w;
    }
    if (t < 64) { sm.m_s[t] = NEG_INF; sm.l_s[t] = 0.f; }

    float O[8][4];
#pragma unroll
    for (int i = 0; i < 8; i++)
#pragma unroll
        for (int j = 0; j < 4; j++) O[i][j] = 0.f;

    const int rg = t & 7;    // 8 q-row groups of 8
    const int cg = t >> 3;   // 16 col groups of 4 (key cols / v cols)

    for (int k0 = 0; k0 < SEQ; k0 += 64) {
        __syncthreads();   // protect Kt/Vs/Pt from previous iteration readers
        // load K (transposed) + V tiles
#pragma unroll
        for (int i = 0; i < 8; i++) {
            int f  = i * 128 + t;
            int c  = f >> 4;
            int d4 = (f & 15) * 4;
            int gi = (base + k0 + c) * DK + d4;
            float4 kv = *(const float4*)&g_K[gi];
            sm.Kt[d4 + 0][c] = kv.x; sm.Kt[d4 + 1][c] = kv.y;
            sm.Kt[d4 + 2][c] = kv.z; sm.Kt[d4 + 3][c] = kv.w;
            *(float4*)&sm.Vs[c][d4] = *(const float4*)&g_V[gi];
        }
        __syncthreads();

        // scores: s[r][c] = Q[r]·K[c] * 0.125
        float s[8][4];
#pragma unroll
        for (int i = 0; i < 8; i++)
#pragma unroll
            for (int j = 0; j < 4; j++) s[i][j] = 0.f;

#pragma unroll 8
        for (int d = 0; d < 64; d++) {
            float4 a0 = *(float4*)&sm.Qt[d][rg * 8];
            float4 a1 = *(float4*)&sm.Qt[d][rg * 8 + 4];
            float4 kk = *(float4*)&sm.Kt[d][cg * 4];
            float a[8] = {a0.x, a0.y, a0.z, a0.w, a1.x, a1.y, a1.z, a1.w};
            float kx[4] = {kk.x, kk.y, kk.z, kk.w};
#pragma unroll
            for (int i = 0; i < 8; i++)
#pragma unroll
                for (int j = 0; j < 4; j++) s[i][j] += a[i] * kx[j];
        }
#pragma unroll
        for (int i = 0; i < 8; i++)
#pragma unroll
            for (int j = 0; j < 4; j++)
                sm.Pt[cg * 4 + j][rg * 8 + i] = s[i][j] * 0.125f;
        __syncthreads();

        // online softmax: 2 threads per q-row
        {
            int r = t >> 1, h = t & 1;
            float m0 = NEG_INF, m1 = NEG_INF, m2 = NEG_INF, m3 = NEG_INF;
#pragma unroll
            for (int c = 0; c < 32; c += 4) {
                m0 = fmaxf(m0, sm.Pt[h * 32 + c + 0][r]);
                m1 = fmaxf(m1, sm.Pt[h * 32 + c + 1][r]);
                m2 = fmaxf(m2, sm.Pt[h * 32 + c + 2][r]);
                m3 = fmaxf(m3, sm.Pt[h * 32 + c + 3][r]);
            }
            sm.pm[t] = fmaxf(fmaxf(m0, m1), fmaxf(m2, m3));
            __syncthreads();

            float mold = sm.m_s[r];
            float mnew = fmaxf(mold, fmaxf(sm.pm[2 * r], sm.pm[2 * r + 1]));
            float s0 = 0.f, s1 = 0.f, s2 = 0.f, s3 = 0.f;
#pragma unroll
            for (int c = 0; c < 32; c += 4) {
                float p0 = __expf(sm.Pt[h * 32 + c + 0][r] - mnew);
                float p1 = __expf(sm.Pt[h * 32 + c + 1][r] - mnew);
                float p2 = __expf(sm.Pt[h * 32 + c + 2][r] - mnew);
                float p3 = __expf(sm.Pt[h * 32 + c + 3][r] - mnew);
                sm.Pt[h * 32 + c + 0][r] = p0; sm.Pt[h * 32 + c + 1][r] = p1;
                sm.Pt[h * 32 + c + 2][r] = p2; sm.Pt[h * 32 + c + 3][r] = p3;
                s0 += p0; s1 += p1; s2 += p2; s3 += p3;
            }
            sm.ps[t] = (s0 + s1) + (s2 + s3);
            __syncthreads();

            if (h == 0) {
                float fct = __expf(mold - mnew);   // 0 on first tile (mold = -inf)
                sm.l_s[r] = sm.l_s[r] * fct + sm.ps[2 * r] + sm.ps[2 * r + 1];
                sm.m_s[r] = mnew;
                sm.fs[r]  = fct;
            }
            __syncthreads();
        }

        // rescale O and accumulate P·V
        float fr[8];
#pragma unroll
        for (int i = 0; i < 8; i++) fr[i] = sm.fs[rg * 8 + i];
#pragma unroll
        for (int i = 0; i < 8; i++)
#pragma unroll
            for (int j = 0; j < 4; j++) O[i][j] *= fr[i];

#pragma unroll 8
        for (int c = 0; c < 64; c++) {
            float4 p0 = *(float4*)&sm.Pt[c][rg * 8];
            float4 p1 = *(float4*)&sm.Pt[c][rg * 8 + 4];
            float4 vv = *(float4*)&sm.Vs[c][cg * 4];
            float p[8] = {p0.x, p0.y, p0.z, p0.w, p1.x, p1.y, p1.z, p1.w};
            float vx[4] = {vv.x, vv.y, vv.z, vv.w};
#pragma unroll
            for (int i = 0; i < 8; i++)
#pragma unroll
                for (int j = 0; j < 4; j++) O[i][j] += p[i] * vx[j];
        }
    }

    // final normalize + store
#pragma unroll
    for (int i = 0; i < 8; i++) {
        int r = rg * 8 + i;
        float inv = 1.0f / sm.l_s[r];
        float4 o = {O[i][0] * inv, O[i][1] * inv, O[i][2] * inv, O[i][3] * inv};
        *(float4*)&out[(base + q0 + r) * DK + cg * 4] = o;
    }
}

// ---------------------------------------------------------------------------
extern "C" void kernel_launch(void* const* d_in, const int* in_sizes, int n_in,
                              void* d_out, int out_size)
{
    const float* q  = (const float*)d_in[0];
    const float* k  = (const float*)d_in[1];
    const float* v  = (const float*)d_in[2];
    const float* Wq = (const float*)d_in[3];
    const float* bq = (const float*)d_in[4];
    const float* Wk = (const float*)d_in[5];
    const float* bk = (const float*)d_in[6];
    const float* Wv = (const float*)d_in[7];
    const float* bv = (const float*)d_in[8];
    float* out = (float*)d_out;

    cudaFuncSetAttribute(attn_kernel, cudaFuncAttributeMaxDynamicSharedMemorySize,
                         (int)sizeof(AttnSmem));

    proj_kernel<<<dim3(BSR / 128, 3), 128>>>(q, k, v, Wq, bq, Wk, bk, Wv, bv);
    attn_kernel<<<dim3(SEQ / 64, NB), 128, sizeof(AttnSmem)>>>(out);
}

// round 2
// speedup vs baseline: 1.2274x; 1.2274x over previous
#include <cuda_runtime.h>

// ---------------------------------------------------------------------------
// AttentionHead: q/k/v projections ([B,S,1024] -> [B,S,64]) + softmax attention
// B=4, S=2048, d_model=1024, d_k=d_v=64, fp32 throughout.
// Round 2: occupancy fix — 256-thread blocks, split-KV(4) flash attention.
// ---------------------------------------------------------------------------

constexpr int DM   = 1024;
constexpr int DK   = 64;
constexpr int SEQ  = 2048;
constexpr int NB   = 4;
constexpr int BSR  = NB * SEQ;       // 8192 rows
constexpr int NSPL = 4;              // KV splits
constexpr int KPS  = SEQ / NSPL;     // 512 keys per split

// Scratch (__device__ globals; no allocation)
__device__ float g_Q[BSR * DK];
__device__ float g_K[BSR * DK];
__device__ float g_V[BSR * DK];
__device__ float g_Op[NSPL * BSR * DK];   // partial (unnormalized) O per split
__device__ float g_m[NSPL * BSR];
__device__ float g_l[NSPL * BSR];

// ---------------------------------------------------------------------------
// Projection: out[r][c] = (sum_k X[r][k] * W[k][c] + b[c]) * scale
// Tile: 128 rows x 64 cols, 256 threads, 8x4 register blocking, K-chunk 32.
// Scale 1/8 folded into the Q projection.
// ---------------------------------------------------------------------------
__global__ __launch_bounds__(256)
void proj_kernel(const float* __restrict__ q, const float* __restrict__ k,
                 const float* __restrict__ v,
                 const float* __restrict__ Wq, const float* __restrict__ bq,
                 const float* __restrict__ Wk, const float* __restrict__ bk,
                 const float* __restrict__ Wv, const float* __restrict__ bv)
{
    __shared__ float Xs[32][132];   // transposed X chunk: Xs[k][row]
    __shared__ float Ws[32][64];    // W chunk: Ws[k][col]

    const int which = blockIdx.y;
    const float* X    = (which == 0) ? q  : (which == 1) ? k  : v;
    const float* W    = (which == 0) ? Wq : (which == 1) ? Wk : Wv;
    const float* bias = (which == 0) ? bq : (which == 1) ? bk : bv;
    float* out        = (which == 0) ? g_Q : (which == 1) ? g_K : g_V;
    const float scale = (which == 0) ? 0.125f : 1.0f;

    const int t  = threadIdx.x;
    const int r0 = blockIdx.x * 128;
    const int rg = t & 15;   // 16 row-groups of 8 rows
    const int cg = t >> 4;   // 16 col-groups of 4 cols

    float acc[8][4];
#pragma unroll
    for (int i = 0; i < 8; i++)
#pragma unroll
        for (int j = 0; j < 4; j++) acc[i][j] = 0.f;

    for (int kk = 0; kk < DM; kk += 32) {
        // X chunk transposed: 1024 float4s, 4 per thread
#pragma unroll
        for (int p = 0; p < 4; p++) {
            int row = p * 32 + (t >> 3);
            int kq  = (t & 7) * 4;
            float4 xv = *(const float4*)&X[(r0 + row) * DM + kk + kq];
            Xs[kq + 0][row] = xv.x; Xs[kq + 1][row] = xv.y;
            Xs[kq + 2][row] = xv.z; Xs[kq + 3][row] = xv.w;
        }
        // W chunk: 512 float4s, 2 per thread
#pragma unroll
        for (int i = 0; i < 2; i++) {
            int f  = i * 256 + t;
            int kr = f >> 4;
            int c4 = (f & 15) * 4;
            *(float4*)&Ws[kr][c4] = *(const float4*)&W[(kk + kr) * DK + c4];
        }
        __syncthreads();

#pragma unroll 8
        for (int kx = 0; kx < 32; kx++) {
            float4 a0 = *(float4*)&Xs[kx][rg * 8];
            float4 a1 = *(float4*)&Xs[kx][rg * 8 + 4];
            float4 bb = *(float4*)&Ws[kx][cg * 4];
            float a[8] = {a0.x, a0.y, a0.z, a0.w, a1.x, a1.y, a1.z, a1.w};
            float b[4] = {bb.x, bb.y, bb.z, bb.w};
#pragma unroll
            for (int i = 0; i < 8; i++)
#pragma unroll
                for (int j = 0; j < 4; j++) acc[i][j] += a[i] * b[j];
        }
        __syncthreads();
    }

    float bc[4];
#pragma unroll
    for (int j = 0; j < 4; j++) bc[j] = bias[cg * 4 + j];

#pragma unroll
    for (int i = 0; i < 8; i++) {
        int r = r0 + rg * 8 + i;
        float4 o = {(acc[i][0] + bc[0]) * scale, (acc[i][1] + bc[1]) * scale,
                    (acc[i][2] + bc[2]) * scale, (acc[i][3] + bc[3]) * scale};
        *(float4*)&out[r * DK + cg * 4] = o;
    }
}

// ---------------------------------------------------------------------------
// Flash attention, split-KV: q-tile 64, k-tile 64, 256 threads.
// Each block handles one (q-tile, batch, kv-split); writes unnormalized O,
// running max m, running sum l to scratch. Combine kernel merges splits.
// ---------------------------------------------------------------------------
struct AttnSmem {
    float Qt[64][68];   // Qt[d][qrow]   (Q pre-scaled by 1/8)
    float Kt[64][68];   // Kt[d][kcol]
    float Pt[64][68];   // Pt[kcol][qrow]
    float Vs[64][64];   // Vs[kcol][v]
    float m_s[64], l_s[64], fs[64];
    float pm[256], ps[256];
};

__global__ __launch_bounds__(256)
void attn_kernel()
{
    extern __shared__ char smraw[];
    AttnSmem& sm = *reinterpret_cast<AttnSmem*>(smraw);

    const int t    = threadIdx.x;
    const int q0   = blockIdx.x * 64;
    const int b    = blockIdx.y;
    const int z    = blockIdx.z;          // KV split
    const int base = b * SEQ;
    const float NEG_INF = __int_as_float(0xff800000u);

    // load Q tile transposed (4 float4/thread)
#pragma unroll
    for (int i = 0; i < 4; i++) {
        int f  = i * 256 + t;
        int r  = f >> 4;
        int d4 = (f & 15) * 4;
        float4 qv = *(const float4*)&g_Q[(base + q0 + r) * DK + d4];
        sm.Qt[d4 + 0][r] = qv.x; sm.Qt[d4 + 1][r] = qv.y;
        sm.Qt[d4 + 2][r] = qv.z; sm.Qt[d4 + 3][r] = qv.w;
    }
    if (t < 64) { sm.m_s[t] = NEG_INF; sm.l_s[t] = 0.f; }

    float O[8][2];
#pragma unroll
    for (int i = 0; i < 8; i++) { O[i][0] = 0.f; O[i][1] = 0.f; }

    const int rg = t & 7;    // 8 q-row groups of 8
    const int cg = t >> 3;   // 32 col groups of 2 (key / v cols)

    for (int k0 = z * KPS; k0 < (z + 1) * KPS; k0 += 64) {
        __syncthreads();   // protect Kt/Vs from previous iteration readers
#pragma unroll
        for (int i = 0; i < 4; i++) {
            int f  = i * 256 + t;
            int c  = f >> 4;
            int d4 = (f & 15) * 4;
            int gi = (base + k0 + c) * DK + d4;
            float4 kv = *(const float4*)&g_K[gi];
            sm.Kt[d4 + 0][c] = kv.x; sm.Kt[d4 + 1][c] = kv.y;
            sm.Kt[d4 + 2][c] = kv.z; sm.Kt[d4 + 3][c] = kv.w;
            *(float4*)&sm.Vs[c][d4] = *(const float4*)&g_V[gi];
        }
        __syncthreads();

        // scores (scale already folded into Q)
        float s[8][2];
#pragma unroll
        for (int i = 0; i < 8; i++) { s[i][0] = 0.f; s[i][1] = 0.f; }

#pragma unroll 8
        for (int d = 0; d < 64; d++) {
            float4 a0 = *(float4*)&sm.Qt[d][rg * 8];
            float4 a1 = *(float4*)&sm.Qt[d][rg * 8 + 4];
            float2 kk = *(float2*)&sm.Kt[d][cg * 2];
            float a[8] = {a0.x, a0.y, a0.z, a0.w, a1.x, a1.y, a1.z, a1.w};
#pragma unroll
            for (int i = 0; i < 8; i++) {
                s[i][0] += a[i] * kk.x;
                s[i][1] += a[i] * kk.y;
            }
        }
#pragma unroll
        for (int i = 0; i < 8; i++) {
            sm.Pt[cg * 2 + 0][rg * 8 + i] = s[i][0];
            sm.Pt[cg * 2 + 1][rg * 8 + i] = s[i][1];
        }
        __syncthreads();

        // online softmax: 4 threads per q-row, 16 cols each
        {
            int r = t >> 2, h = t & 3;
            float m0 = NEG_INF, m1 = NEG_INF, m2 = NEG_INF, m3 = NEG_INF;
#pragma unroll
            for (int c = 0; c < 16; c += 4) {
                m0 = fmaxf(m0, sm.Pt[h * 16 + c + 0][r]);
                m1 = fmaxf(m1, sm.Pt[h * 16 + c + 1][r]);
                m2 = fmaxf(m2, sm.Pt[h * 16 + c + 2][r]);
                m3 = fmaxf(m3, sm.Pt[h * 16 + c + 3][r]);
            }
            sm.pm[t] = fmaxf(fmaxf(m0, m1), fmaxf(m2, m3));
            __syncthreads();

            float mold = sm.m_s[r];
            float mnew = fmaxf(fmaxf(mold, fmaxf(sm.pm[4 * r], sm.pm[4 * r + 1])),
                               fmaxf(sm.pm[4 * r + 2], sm.pm[4 * r + 3]));
            float s0 = 0.f, s1 = 0.f, s2 = 0.f, s3 = 0.f;
#pragma unroll
            for (int c = 0; c < 16; c += 4) {
                float p0 = __expf(sm.Pt[h * 16 + c + 0][r] - mnew);
                float p1 = __expf(sm.Pt[h * 16 + c + 1][r] - mnew);
                float p2 = __expf(sm.Pt[h * 16 + c + 2][r] - mnew);
                float p3 = __expf(sm.Pt[h * 16 + c + 3][r] - mnew);
                sm.Pt[h * 16 + c + 0][r] = p0; sm.Pt[h * 16 + c + 1][r] = p1;
                sm.Pt[h * 16 + c + 2][r] = p2; sm.Pt[h * 16 + c + 3][r] = p3;
                s0 += p0; s1 += p1; s2 += p2; s3 += p3;
            }
            sm.ps[t] = (s0 + s1) + (s2 + s3);
            __syncthreads();

            if (h == 0) {
                float fct = __expf(mold - mnew);   // 0 on first tile
                sm.l_s[r] = sm.l_s[r] * fct +
                            (sm.ps[4 * r] + sm.ps[4 * r + 1]) +
                            (sm.ps[4 * r + 2] + sm.ps[4 * r + 3]);
                sm.m_s[r] = mnew;
                sm.fs[r]  = fct;
            }
            __syncthreads();
        }

        // rescale O and accumulate P·V
#pragma unroll
        for (int i = 0; i < 8; i++) {
            float fr = sm.fs[rg * 8 + i];
            O[i][0] *= fr; O[i][1] *= fr;
        }
#pragma unroll 8
        for (int c = 0; c < 64; c++) {
            float4 p0 = *(float4*)&sm.Pt[c][rg * 8];
            float4 p1 = *(float4*)&sm.Pt[c][rg * 8 + 4];
            float2 vv = *(float2*)&sm.Vs[c][cg * 2];
            float p[8] = {p0.x, p0.y, p0.z, p0.w, p1.x, p1.y, p1.z, p1.w};
#pragma unroll
            for (int i = 0; i < 8; i++) {
                O[i][0] += p[i] * vv.x;
                O[i][1] += p[i] * vv.y;
            }
        }
    }

    // write unnormalized partial + (m, l)
#pragma unroll
    for (int i = 0; i < 8; i++) {
        int gr = base + q0 + rg * 8 + i;
        float2 o = {O[i][0], O[i][1]};
        *(float2*)&g_Op[(z * BSR + gr) * DK + cg * 2] = o;
    }
    if (t < 64) {
        int gr = base + q0 + t;
        g_m[z * BSR + gr] = sm.m_s[t];
        g_l[z * BSR + gr] = sm.l_s[t];
    }
}

// ---------------------------------------------------------------------------
// Combine: merge NSPL split partials per row via logsumexp weighting.
// One thread per (row, 4 cols): 8192*16 threads.
// ---------------------------------------------------------------------------
__global__ __launch_bounds__(256)
void combine_kernel(float* __restrict__ out)
{
    int gid = blockIdx.x * 256 + threadIdx.x;
    int row = gid >> 4;
    int c4  = (gid & 15) * 4;

    float m[NSPL], w[NSPL];
#pragma unroll
    for (int i = 0; i < NSPL; i++) m[i] = g_m[i * BSR + row];
    float M = fmaxf(fmaxf(m[0], m[1]), fmaxf(m[2], m[3]));

    float denom = 0.f;
#pragma unroll
    for (int i = 0; i < NSPL; i++) {
        w[i] = __expf(m[i] - M);
        denom += w[i] * g_l[i * BSR + row];
    }
    float inv = 1.0f / denom;

    float4 acc = {0.f, 0.f, 0.f, 0.f};
#pragma unroll
    for (int i = 0; i < NSPL; i++) {
        float4 o = *(const float4*)&g_Op[(i * BSR + row) * DK + c4];
        acc.x += w[i] * o.x; acc.y += w[i] * o.y;
        acc.z += w[i] * o.z; acc.w += w[i] * o.w;
    }
    float4 r = {acc.x * inv, acc.y * inv, acc.z * inv, acc.w * inv};
    *(float4*)&out[row * DK + c4] = r;
}

// ---------------------------------------------------------------------------
extern "C" void kernel_launch(void* const* d_in, const int* in_sizes, int n_in,
                              void* d_out, int out_size)
{
    const float* q  = (const float*)d_in[0];
    const float* k  = (const float*)d_in[1];
    const float* v  = (const float*)d_in[2];
    const float* Wq = (const float*)d_in[3];
    const float* bq = (const float*)d_in[4];
    const float* Wk = (const float*)d_in[5];
    const float* bk = (const float*)d_in[6];
    const float* Wv = (const float*)d_in[7];
    const float* bv = (const float*)d_in[8];
    float* out = (float*)d_out;

    cudaFuncSetAttribute(attn_kernel, cudaFuncAttributeMaxDynamicSharedMemorySize,
                         (int)sizeof(AttnSmem));

    proj_kernel<<<dim3(BSR / 128, 3), 256>>>(q, k, v, Wq, bq, Wk, bk, Wv, bv);
    attn_kernel<<<dim3(SEQ / 64, NB, NSPL), 256, sizeof(AttnSmem)>>>();
    combine_kernel<<<(BSR * 16) / 256, 256>>>(out);
}

// round 6
// speedup vs baseline: 2.7641x; 2.2520x over previous
#include <cuda_runtime.h>
#include <cstdint>

// ---------------------------------------------------------------------------
// AttentionHead: q/k/v projections ([B,S,1024] -> [B,S,64]) + softmax attention
// Round 5: everything on mma.sync.m16n8k8 tf32 (3-term hi/lo split ~ fp32),
// polynomial exp on the FMA pipe (MUFU floor removed).
// ---------------------------------------------------------------------------

constexpr int DM   = 1024;
constexpr int DK   = 64;
constexpr int SEQ  = 2048;
constexpr int NB   = 4;
constexpr int BSR  = NB * SEQ;       // 8192 rows
constexpr int NSPL = 4;              // KV splits
constexpr int KPS  = SEQ / NSPL;     // 512 keys per split

// Scratch (__device__ globals; no allocation)
__device__ float g_Q[BSR * DK];
__device__ float g_K[BSR * DK];
__device__ float g_V[BSR * DK];
__device__ float g_Op[NSPL * BSR * DK];
__device__ float g_m[NSPL * BSR];
__device__ float g_l[NSPL * BSR];
// Pre-transposed + tf32-split weights: [mat][n][k] (n-major, K contiguous)
__device__ float g_Wth[3][DK * DM];
__device__ float g_Wtl[3][DK * DM];

// ---------------------------------------------------------------------------
// Helpers
// ---------------------------------------------------------------------------
__device__ __forceinline__ float tf32r(float x) {
    uint32_t u;
    asm("cvt.rna.tf32.f32 %0, %1;" : "=r"(u) : "f"(x));
    return __uint_as_float(u);
}
__device__ __forceinline__ void split2(float x, uint32_t& h, uint32_t& l) {
    float fh = tf32r(x);
    h = __float_as_uint(fh);
    l = __float_as_uint(tf32r(x - fh));
}
// D = A(16x8 tf32) * B(8x8 tf32) + D, fp32 accum
__device__ __forceinline__ void mma8(float c[4], const uint32_t a[4],
                                     const uint32_t b[2]) {
    asm volatile(
        "mma.sync.aligned.m16n8k8.row.col.f32.tf32.tf32.f32 "
        "{%0,%1,%2,%3}, {%4,%5,%6,%7}, {%8,%9}, {%0,%1,%2,%3};"
        : "+f"(c[0]), "+f"(c[1]), "+f"(c[2]), "+f"(c[3])
        : "r"(a[0]), "r"(a[1]), "r"(a[2]), "r"(a[3]), "r"(b[0]), "r"(b[1]));
}
// exp(x) for x <= 0 on the FMA pipe (no MUFU). |err| ~ 1e-7 rel.
__device__ __forceinline__ float fexp(float x) {
    x = fmaxf(x, -80.0f);
    float t = x * 1.4426950408889634f;
    float r = rintf(t);
    float f = t - r;
    float p = 1.3333558146428443e-3f;
    p = fmaf(p, f, 9.6181291076284772e-3f);
    p = fmaf(p, f, 5.5504108664821580e-2f);
    p = fmaf(p, f, 2.4022650695910072e-1f);
    p = fmaf(p, f, 6.9314718055994531e-1f);
    p = fmaf(p, f, 1.0f);
    int ir = (int)r;
    return __int_as_float(__float_as_int(p) + (ir << 23));
}

// ---------------------------------------------------------------------------
// Weight prep: transpose W [1024][64] -> Wt [64][1024], split into tf32 hi/lo.
// ---------------------------------------------------------------------------
__global__ __launch_bounds__(256)
void w_prep(const float* __restrict__ Wq, const float* __restrict__ Wk,
            const float* __restrict__ Wv)
{
    __shared__ float tile[64][65];
    const int mat = blockIdx.y;
    const float* W = (mat == 0) ? Wq : (mat == 1) ? Wk : Wv;
    const int k0 = blockIdx.x * 64;
    const int t  = threadIdx.x;

#pragma unroll
    for (int i = 0; i < 4; i++) {
        int f  = i * 256 + t;
        int kr = f >> 4;
        int n4 = (f & 15) * 4;
        float4 w = *(const float4*)&W[(k0 + kr) * DK + n4];
        tile[kr][n4 + 0] = w.x; tile[kr][n4 + 1] = w.y;
        tile[kr][n4 + 2] = w.z; tile[kr][n4 + 3] = w.w;
    }
    __syncthreads();
#pragma unroll
    for (int i = 0; i < 4; i++) {
        int f  = i * 256 + t;
        int n  = f >> 4;
        int k4 = (f & 15) * 4;
        float4 h, l;
        float v0 = tile[k4 + 0][n], v1 = tile[k4 + 1][n];
        float v2 = tile[k4 + 2][n], v3 = tile[k4 + 3][n];
        h.x = tf32r(v0); l.x = tf32r(v0 - h.x);
        h.y = tf32r(v1); l.y = tf32r(v1 - h.y);
        h.z = tf32r(v2); l.z = tf32r(v2 - h.z);
        h.w = tf32r(v3); l.w = tf32r(v3 - h.w);
        *(float4*)&g_Wth[mat][n * DM + k0 + k4] = h;
        *(float4*)&g_Wtl[mat][n * DM + k0 + k4] = l;
    }
}

// ---------------------------------------------------------------------------
// Projection on mma.sync tf32. Per CTA: 64 rows x 64 cols, K=1024 (chunks of
// 32). 8 warps: warp = (mt = w&3 -> 16 rows, nh = w>>2 -> 32 cols).
// ---------------------------------------------------------------------------
__global__ __launch_bounds__(256)
void proj_mma(const float* __restrict__ q, const float* __restrict__ k,
              const float* __restrict__ v,
              const float* __restrict__ bq, const float* __restrict__ bk,
              const float* __restrict__ bv)
{
    __shared__ float Ah[64][36], Al[64][36];   // [row][k]
    __shared__ float Bh[64][36], Bl[64][36];   // [n][k]

    const int t    = threadIdx.x;
    const int w    = t >> 5;
    const int lane = t & 31;
    const int mat  = blockIdx.y;
    const int r0   = blockIdx.x * 64;

    const float* X    = (mat == 0) ? q  : (mat == 1) ? k  : v;
    const float* bias = (mat == 0) ? bq : (mat == 1) ? bk : bv;
    float* out        = (mat == 0) ? g_Q : (mat == 1) ? g_K : g_V;
    const float scale = (mat == 0) ? 0.125f : 1.0f;
    const float* Wh = g_Wth[mat];
    const float* Wl = g_Wtl[mat];

    const int mt = w & 3, nh = w >> 2;
    float c[4][4];
#pragma unroll
    for (int i = 0; i < 4; i++)
#pragma unroll
        for (int j = 0; j < 4; j++) c[i][j] = 0.f;

    for (int kk = 0; kk < DM; kk += 32) {
        // stage A (split) : 64x32 floats = 512 float4, 2/thread
#pragma unroll
        for (int i = 0; i < 2; i++) {
            int f = i * 256 + t, row = f >> 3, k4 = (f & 7) * 4;
            float4 x = *(const float4*)&X[(r0 + row) * DM + kk + k4];
            float4 h, l;
            h.x = tf32r(x.x); l.x = tf32r(x.x - h.x);
            h.y = tf32r(x.y); l.y = tf32r(x.y - h.y);
            h.z = tf32r(x.z); l.z = tf32r(x.z - h.z);
            h.w = tf32r(x.w); l.w = tf32r(x.w - h.w);
            *(float4*)&Ah[row][k4] = h;
            *(float4*)&Al[row][k4] = l;
        }
        // stage B (pre-split in gmem): 2 float4/thread each
#pragma unroll
        for (int i = 0; i < 2; i++) {
            int f = i * 256 + t, n = f >> 3, k4 = (f & 7) * 4;
            *(float4*)&Bh[n][k4] = *(const float4*)&Wh[n * DM + kk + k4];
            *(float4*)&Bl[n][k4] = *(const float4*)&Wl[n * DM + kk + k4];
        }
        __syncthreads();

#pragma unroll
        for (int ks = 0; ks < 4; ks++) {
            const int row = mt * 16 + (lane >> 2);
            const int kb  = ks * 8 + (lane & 3);
            uint32_t ah[4], al[4];
            ah[0] = __float_as_uint(Ah[row][kb]);
            ah[1] = __float_as_uint(Ah[row + 8][kb]);
            ah[2] = __float_as_uint(Ah[row][kb + 4]);
            ah[3] = __float_as_uint(Ah[row + 8][kb + 4]);
            al[0] = __float_as_uint(Al[row][kb]);
            al[1] = __float_as_uint(Al[row + 8][kb]);
            al[2] = __float_as_uint(Al[row][kb + 4]);
            al[3] = __float_as_uint(Al[row + 8][kb + 4]);
#pragma unroll
            for (int nt = 0; nt < 4; nt++) {
                const int n = nh * 32 + nt * 8 + (lane >> 2);
                uint32_t bh[2], bl[2];
                bh[0] = __float_as_uint(Bh[n][kb]);
                bh[1] = __float_as_uint(Bh[n][kb + 4]);
                bl[0] = __float_as_uint(Bl[n][kb]);
                bl[1] = __float_as_uint(Bl[n][kb + 4]);
                mma8(c[nt], ah, bh);
                mma8(c[nt], ah, bl);
                mma8(c[nt], al, bh);
            }
        }
        __syncthreads();
    }

    // epilogue
    const int row0 = r0 + mt * 16 + (lane >> 2);
#pragma unroll
    for (int nt = 0; nt < 4; nt++) {
        const int col = nh * 32 + nt * 8 + 2 * (lane & 3);
        float b0 = bias[col], b1 = bias[col + 1];
        float2 o0 = {(c[nt][0] + b0) * scale, (c[nt][1] + b1) * scale};
        float2 o1 = {(c[nt][2] + b0) * scale, (c[nt][3] + b1) * scale};
        *(float2*)&out[row0 * DK + col]       = o0;
        *(float2*)&out[(row0 + 8) * DK + col] = o1;
    }
}

// ---------------------------------------------------------------------------
// Flash attention, split-KV, tensor-core QK^T and PV (3-term tf32 split).
// q-tile 64, k-tile 64, 256 threads; warp = (mt = w&3, nh = w>>2).
// ---------------------------------------------------------------------------
struct ASmem {
    float Qh[64][68];   // [qrow][d]  tf32-hi of Q (pre-scaled by 1/8)
    float Ql[64][68];   // [qrow][d]  tf32-lo
    float Kt[64][68];   // [d][kcol]  fp32
    float Pt[64][68];   // [kcol][qrow] scores -> probs, fp32
    float Vs[64][68];   // [kcol][v]  fp32
    float m_s[64], l_s[64], fs[64];
    float pm[256], ps[256];
};

__global__ __launch_bounds__(256, 2)
void attn_kernel()
{
    extern __shared__ char smraw[];
    ASmem& sm = *reinterpret_cast<ASmem*>(smraw);

    const int t    = threadIdx.x;
    const int w    = t >> 5;
    const int lane = t & 31;
    const int q0   = blockIdx.x * 64;
    const int b    = blockIdx.y;
    const int z    = blockIdx.z;
    const int base = b * SEQ;
    const float NEG_INF = __int_as_float(0xff800000u);
    const int mt = w & 3, nh = w >> 2;

    // load + split Q tile (4 float4/thread)
#pragma unroll
    for (int i = 0; i < 4; i++) {
        int f  = i * 256 + t;
        int r  = f >> 4;
        int d4 = (f & 15) * 4;
        float4 qv = *(const float4*)&g_Q[(base + q0 + r) * DK + d4];
        float4 h, l;
        h.x = tf32r(qv.x); l.x = tf32r(qv.x - h.x);
        h.y = tf32r(qv.y); l.y = tf32r(qv.y - h.y);
        h.z = tf32r(qv.z); l.z = tf32r(qv.z - h.z);
        h.w = tf32r(qv.w); l.w = tf32r(qv.w - h.w);
        *(float4*)&sm.Qh[r][d4] = h;
        *(float4*)&sm.Ql[r][d4] = l;
    }
    if (t < 64) { sm.m_s[t] = NEG_INF; sm.l_s[t] = 0.f; }

    float o[4][4];
#pragma unroll
    for (int i = 0; i < 4; i++)
#pragma unroll
        for (int j = 0; j < 4; j++) o[i][j] = 0.f;

    for (int k0 = z * KPS; k0 < (z + 1) * KPS; k0 += 64) {
        __syncthreads();   // protect Kt/Vs/Pt from previous iteration readers
        // stage K (transposed) + V
#pragma unroll
        for (int i = 0; i < 4; i++) {
            int f  = i * 256 + t;
            int c  = f >> 4;
            int d4 = (f & 15) * 4;
            int gi = (base + k0 + c) * DK + d4;
            float4 kv = *(const float4*)&g_K[gi];
            sm.Kt[d4 + 0][c] = kv.x; sm.Kt[d4 + 1][c] = kv.y;
            sm.Kt[d4 + 2][c] = kv.z; sm.Kt[d4 + 3][c] = kv.w;
            *(float4*)&sm.Vs[c][d4] = *(const float4*)&g_V[gi];
        }
        __syncthreads();

        // ---- S = Q K^T (tensor) ----
        float s[4][4];
#pragma unroll
        for (int i = 0; i < 4; i++)
#pragma unroll
            for (int j = 0; j < 4; j++) s[i][j] = 0.f;

#pragma unroll
        for (int ks = 0; ks < 8; ks++) {
            const int qr = mt * 16 + (lane >> 2);
            const int kb = ks * 8 + (lane & 3);
            uint32_t ah[4], al[4];
            ah[0] = __float_as_uint(sm.Qh[qr][kb]);
            ah[1] = __float_as_uint(sm.Qh[qr + 8][kb]);
            ah[2] = __float_as_uint(sm.Qh[qr][kb + 4]);
            ah[3] = __float_as_uint(sm.Qh[qr + 8][kb + 4]);
            al[0] = __float_as_uint(sm.Ql[qr][kb]);
            al[1] = __float_as_uint(sm.Ql[qr + 8][kb]);
            al[2] = __float_as_uint(sm.Ql[qr][kb + 4]);
            al[3] = __float_as_uint(sm.Ql[qr + 8][kb + 4]);
#pragma unroll
            for (int nt = 0; nt < 4; nt++) {
                const int n = nh * 32 + nt * 8 + (lane >> 2);
                uint32_t bh[2], bl[2];
                split2(sm.Kt[kb][n],     bh[0], bl[0]);
                split2(sm.Kt[kb + 4][n], bh[1], bl[1]);
                mma8(s[nt], ah, bh);
                mma8(s[nt], ah, bl);
                mma8(s[nt], al, bh);
            }
        }
        // write S -> Pt[kcol][qrow]
        {
            const int qr = mt * 16 + (lane >> 2);
#pragma unroll
            for (int nt = 0; nt < 4; nt++) {
                const int col = nh * 32 + nt * 8 + 2 * (lane & 3);
                sm.Pt[col][qr]         = s[nt][0];
                sm.Pt[col + 1][qr]     = s[nt][1];
                sm.Pt[col][qr + 8]     = s[nt][2];
                sm.Pt[col + 1][qr + 8] = s[nt][3];
            }
        }
        __syncthreads();

        // ---- online softmax (4 threads per q-row, 16 cols each) ----
        {
            int r = t >> 2, h = t & 3;
            float m0 = NEG_INF, m1 = NEG_INF, m2 = NEG_INF, m3 = NEG_INF;
#pragma unroll
            for (int c = 0; c < 16; c += 4) {
                m0 = fmaxf(m0, sm.Pt[h * 16 + c + 0][r]);
                m1 = fmaxf(m1, sm.Pt[h * 16 + c + 1][r]);
                m2 = fmaxf(m2, sm.Pt[h * 16 + c + 2][r]);
                m3 = fmaxf(m3, sm.Pt[h * 16 + c + 3][r]);
            }
            sm.pm[t] = fmaxf(fmaxf(m0, m1), fmaxf(m2, m3));
            __syncthreads();

            float mold = sm.m_s[r];
            float mnew = fmaxf(fmaxf(mold, fmaxf(sm.pm[4 * r], sm.pm[4 * r + 1])),
                               fmaxf(sm.pm[4 * r + 2], sm.pm[4 * r + 3]));
            float s0 = 0.f, s1 = 0.f, s2 = 0.f, s3 = 0.f;
#pragma unroll
            for (int c = 0; c < 16; c += 4) {
                float p0 = fexp(sm.Pt[h * 16 + c + 0][r] - mnew);
                float p1 = fexp(sm.Pt[h * 16 + c + 1][r] - mnew);
                float p2 = fexp(sm.Pt[h * 16 + c + 2][r] - mnew);
                float p3 = fexp(sm.Pt[h * 16 + c + 3][r] - mnew);
                sm.Pt[h * 16 + c + 0][r] = p0; sm.Pt[h * 16 + c + 1][r] = p1;
                sm.Pt[h * 16 + c + 2][r] = p2; sm.Pt[h * 16 + c + 3][r] = p3;
                s0 += p0; s1 += p1; s2 += p2; s3 += p3;
            }
            sm.ps[t] = (s0 + s1) + (s2 + s3);
            __syncthreads();

            if (h == 0) {
                float fct = fexp(mold - mnew);
                sm.l_s[r] = sm.l_s[r] * fct +
                            (sm.ps[4 * r] + sm.ps[4 * r + 1]) +
                            (sm.ps[4 * r + 2] + sm.ps[4 * r + 3]);
                sm.m_s[r] = mnew;
                sm.fs[r]  = fct;
            }
            __syncthreads();
        }

        // ---- rescale O, accumulate P V (tensor) ----
        {
            const int qr = mt * 16 + (lane >> 2);
            float f0 = sm.fs[qr], f1 = sm.fs[qr + 8];
#pragma unroll
            for (int nt = 0; nt < 4; nt++) {
                o[nt][0] *= f0; o[nt][1] *= f0;
                o[nt][2] *= f1; o[nt][3] *= f1;
            }
        }
#pragma unroll
        for (int ks = 0; ks < 8; ks++) {
            const int qr = mt * 16 + (lane >> 2);
            const int kc = ks * 8 + (lane & 3);
            uint32_t pah[4], pal[4];
            split2(sm.Pt[kc][qr],         pah[0], pal[0]);
            split2(sm.Pt[kc][qr + 8],     pah[1], pal[1]);
            split2(sm.Pt[kc + 4][qr],     pah[2], pal[2]);
            split2(sm.Pt[kc + 4][qr + 8], pah[3], pal[3]);
#pragma unroll
            for (int nt = 0; nt < 4; nt++) {
                const int n = nh * 32 + nt * 8 + (lane >> 2);
                uint32_t vh[2], vl[2];
                split2(sm.Vs[kc][n],     vh[0], vl[0]);
                split2(sm.Vs[kc + 4][n], vh[1], vl[1]);
                mma8(o[nt], pah, vh);
                mma8(o[nt], pah, vl);
                mma8(o[nt], pal, vh);
            }
        }
    }

    // epilogue: normalize by l, write partial + (m, l)
    {
        const int qr = mt * 16 + (lane >> 2);
        float inv0 = 1.0f / sm.l_s[qr];
        float inv1 = 1.0f / sm.l_s[qr + 8];
        const int gr0 = base + q0 + qr;
#pragma unroll
        for (int nt = 0; nt < 4; nt++) {
            const int col = nh * 32 + nt * 8 + 2 * (lane & 3);
            float2 o0 = {o[nt][0] * inv0, o[nt][1] * inv0};
            float2 o1 = {o[nt][2] * inv1, o[nt][3] * inv1};
            *(float2*)&g_Op[(z * BSR + gr0) * DK + col]     = o0;
            *(float2*)&g_Op[(z * BSR + gr0 + 8) * DK + col] = o1;
        }
    }
    if (t < 64) {
        int gr = base + q0 + t;
        g_m[z * BSR + gr] = sm.m_s[t];
        g_l[z * BSR + gr] = sm.l_s[t];
    }
}

// ---------------------------------------------------------------------------
// Combine: merge NSPL split partials per row (logsumexp weighting).
// ---------------------------------------------------------------------------
__global__ __launch_bounds__(256)
void combine_kernel(float* __restrict__ out)
{
    int gid = blockIdx.x * 256 + threadIdx.x;
    int row = gid >> 4;
    int c4  = (gid & 15) * 4;

    float m[NSPL], ww[NSPL];
#pragma unroll
    for (int i = 0; i < NSPL; i++) m[i] = g_m[i * BSR + row];
    float M = fmaxf(fmaxf(m[0], m[1]), fmaxf(m[2], m[3]));

    float denom = 0.f;
#pragma unroll
    for (int i = 0; i < NSPL; i++) {
        ww[i] = fexp(m[i] - M);
        denom += ww[i] * g_l[i * BSR + row];
    }
    float inv = 1.0f / denom;

    float4 acc = {0.f, 0.f, 0.f, 0.f};
#pragma unroll
    for (int i = 0; i < NSPL; i++) {
        float wl = ww[i] * g_l[i * BSR + row];
        float4 ov = *(const float4*)&g_Op[(i * BSR + row) * DK + c4];
        acc.x += wl * ov.x; acc.y += wl * ov.y;
        acc.z += wl * ov.z; acc.w += wl * ov.w;
    }
    float4 r = {acc.x * inv, acc.y * inv, acc.z * inv, acc.w * inv};
    *(float4*)&out[row * DK + c4] = r;
}

// ---------------------------------------------------------------------------
extern "C" void kernel_launch(void* const* d_in, const int* in_sizes, int n_in,
                              void* d_out, int out_size)
{
    const float* q  = (const float*)d_in[0];
    const float* k  = (const float*)d_in[1];
    const float* v  = (const float*)d_in[2];
    const float* Wq = (const float*)d_in[3];
    const float* bq = (const float*)d_in[4];
    const float* Wk = (const float*)d_in[5];
    const float* bk = (const float*)d_in[6];
    const float* Wv = (const float*)d_in[7];
    const float* bv = (const float*)d_in[8];
    float* out = (float*)d_out;

    cudaFuncSetAttribute(attn_kernel, cudaFuncAttributeMaxDynamicSharedMemorySize,
                         (int)sizeof(ASmem));

    w_prep<<<dim3(DM / 64, 3), 256>>>(Wq, Wk, Wv);
    proj_mma<<<dim3(BSR / 64, 3), 256>>>(q, k, v, bq, bk, bv);
    attn_kernel<<<dim3(SEQ / 64, NB, NSPL), 256, sizeof(ASmem)>>>();
    combine_kernel<<<(BSR * 16) / 256, 256>>>(out);
}

// round 7
// speedup vs baseline: 5.6545x; 2.0457x over previous
#include <cuda_runtime.h>
#include <cstdint>

// ---------------------------------------------------------------------------
// AttentionHead: q/k/v projections ([B,S,1024] -> [B,S,64]) + softmax attention
// Round 7: bf16 m16n8k16 mma.sync with 2-term hi/lo split (~1e-5 accuracy),
// register-resident softmax (P never touches smem), split-KV(4).
// ---------------------------------------------------------------------------

constexpr int DM   = 1024;
constexpr int DK   = 64;
constexpr int SEQ  = 2048;
constexpr int NB   = 4;
constexpr int BSR  = NB * SEQ;
constexpr int NSPL = 4;
constexpr int KPS  = SEQ / NSPL;

// Scratch (__device__ globals; no allocation)
__device__ float g_Q[BSR * DK];
__device__ float g_K[BSR * DK];
__device__ float g_V[BSR * DK];
__device__ float g_Op[NSPL * BSR * DK];
__device__ float g_m[NSPL * BSR];
__device__ float g_l[NSPL * BSR];
// Pre-transposed, bf16-pair-packed weights: [mat][n][kpair] (512 pairs per n)
__device__ uint32_t g_Wph[3][DK * DM / 2];
__device__ uint32_t g_Wpl[3][DK * DM / 2];

// ---------------------------------------------------------------------------
// Helpers
// ---------------------------------------------------------------------------
__device__ __forceinline__ uint32_t packbf(float lo, float hi) {
    uint32_t r;
    asm("cvt.rn.bf16x2.f32 %0, %1, %2;" : "=r"(r) : "f"(hi), "f"(lo));
    return r;
}
// x0 -> lower bf16, x1 -> upper bf16; l = bf16 residuals
__device__ __forceinline__ void split_pair(float x0, float x1,
                                           uint32_t& h, uint32_t& l) {
    h = packbf(x0, x1);
    float h0 = __uint_as_float(h << 16);
    float h1 = __uint_as_float(h & 0xffff0000u);
    l = packbf(x0 - h0, x1 - h1);
}
// D(16x8) += A(16x16 bf16) * B(16x8 bf16), fp32 accum
__device__ __forceinline__ void mma16(float c[4], const uint32_t a[4],
                                      const uint32_t b[2]) {
    asm volatile(
        "mma.sync.aligned.m16n8k16.row.col.f32.bf16.bf16.f32 "
        "{%0,%1,%2,%3}, {%4,%5,%6,%7}, {%8,%9}, {%0,%1,%2,%3};"
        : "+f"(c[0]), "+f"(c[1]), "+f"(c[2]), "+f"(c[3])
        : "r"(a[0]), "r"(a[1]), "r"(a[2]), "r"(a[3]), "r"(b[0]), "r"(b[1]));
}
// exp(x), x <= 0, FMA pipe only
__device__ __forceinline__ float fexp(float x) {
    x = fmaxf(x, -80.0f);
    float t = x * 1.4426950408889634f;
    float r = rintf(t);
    float f = t - r;
    float p = 1.3333558146428443e-3f;
    p = fmaf(p, f, 9.6181291076284772e-3f);
    p = fmaf(p, f, 5.5504108664821580e-2f);
    p = fmaf(p, f, 2.4022650695910072e-1f);
    p = fmaf(p, f, 6.9314718055994531e-1f);
    p = fmaf(p, f, 1.0f);
    return __int_as_float(__float_as_int(p) + ((int)r << 23));
}

// ---------------------------------------------------------------------------
// Weight prep: transpose W [1024][64] -> [64][1024], pack bf16 hi/lo k-pairs.
// ---------------------------------------------------------------------------
__global__ __launch_bounds__(256)
void w_prep(const float* __restrict__ Wq, const float* __restrict__ Wk,
            const float* __restrict__ Wv)
{
    __shared__ float tile[64][65];
    const int mat = blockIdx.y;
    const float* W = (mat == 0) ? Wq : (mat == 1) ? Wk : Wv;
    const int k0 = blockIdx.x * 64;
    const int t  = threadIdx.x;

#pragma unroll
    for (int i = 0; i < 4; i++) {
        int f  = i * 256 + t;
        int kr = f >> 4;
        int n4 = (f & 15) * 4;
        float4 w = *(const float4*)&W[(k0 + kr) * DK + n4];
        tile[kr][n4 + 0] = w.x; tile[kr][n4 + 1] = w.y;
        tile[kr][n4 + 2] = w.z; tile[kr][n4 + 3] = w.w;
    }
    __syncthreads();
#pragma unroll
    for (int i = 0; i < 4; i++) {
        int f  = i * 256 + t;
        int n  = f >> 4;
        int k4 = (f & 15) * 4;
        uint32_t h0, l0, h1, l1;
        split_pair(tile[k4][n],     tile[k4 + 1][n], h0, l0);
        split_pair(tile[k4 + 2][n], tile[k4 + 3][n], h1, l1);
        int idx = n * (DM / 2) + ((k0 + k4) >> 1);
        g_Wph[mat][idx] = h0; g_Wph[mat][idx + 1] = h1;
        g_Wpl[mat][idx] = l0; g_Wpl[mat][idx + 1] = l1;
    }
}

// ---------------------------------------------------------------------------
// Projection: 64 rows x 64 cols per CTA, K chunks of 64, bf16 split MMA.
// 8 warps: (mt = w&3 -> 16 rows, nh = w>>2 -> 32 cols).
// ---------------------------------------------------------------------------
__global__ __launch_bounds__(256)
void proj_mma(const float* __restrict__ q, const float* __restrict__ k,
              const float* __restrict__ v,
              const float* __restrict__ bq, const float* __restrict__ bk,
              const float* __restrict__ bv)
{
    __shared__ uint32_t Ah[64][36], Al[64][36];   // [row][kpair]
    __shared__ uint32_t Bh[64][36], Bl[64][36];   // [n][kpair]

    const int t    = threadIdx.x;
    const int w    = t >> 5;
    const int lane = t & 31;
    const int kp   = lane & 3;
    const int ln4  = lane >> 2;
    const int mat  = blockIdx.y;
    const int r0   = blockIdx.x * 64;

    const float* X    = (mat == 0) ? q  : (mat == 1) ? k  : v;
    const float* bias = (mat == 0) ? bq : (mat == 1) ? bk : bv;
    float* out        = (mat == 0) ? g_Q : (mat == 1) ? g_K : g_V;
    const float scale = (mat == 0) ? 0.125f : 1.0f;
    const uint32_t* Wh = g_Wph[mat];
    const uint32_t* Wl = g_Wpl[mat];

    const int mt = w & 3, nh = w >> 2;
    const int arow = mt * 16 + ln4;

    float c[4][4];
#pragma unroll
    for (int i = 0; i < 4; i++)
#pragma unroll
        for (int j = 0; j < 4; j++) c[i][j] = 0.f;

    for (int kk = 0; kk < DM; kk += 64) {
        // stage A: 1024 float4, 4/thread, split+pack
#pragma unroll
        for (int i = 0; i < 4; i++) {
            int f = i * 256 + t, row = f >> 4, k4 = (f & 15) * 4;
            float4 x = *(const float4*)&X[(r0 + row) * DM + kk + k4];
            uint32_t h0, l0, h1, l1;
            split_pair(x.x, x.y, h0, l0);
            split_pair(x.z, x.w, h1, l1);
            *(uint2*)&Ah[row][k4 >> 1] = make_uint2(h0, h1);
            *(uint2*)&Al[row][k4 >> 1] = make_uint2(l0, l1);
        }
        // stage B: pre-packed, 2 uint4/thread each
#pragma unroll
        for (int i = 0; i < 2; i++) {
            int f = i * 256 + t, n = f >> 3, p4 = (f & 7) * 4;
            *(uint4*)&Bh[n][p4] = *(const uint4*)&Wh[n * (DM / 2) + (kk >> 1) + p4];
            *(uint4*)&Bl[n][p4] = *(const uint4*)&Wl[n * (DM / 2) + (kk >> 1) + p4];
        }
        __syncthreads();

#pragma unroll
        for (int ks = 0; ks < 4; ks++) {
            const int ci = ks * 8 + kp;
            uint32_t ah[4] = {Ah[arow][ci], Ah[arow + 8][ci],
                              Ah[arow][ci + 4], Ah[arow + 8][ci + 4]};
            uint32_t al[4] = {Al[arow][ci], Al[arow + 8][ci],
                              Al[arow][ci + 4], Al[arow + 8][ci + 4]};
#pragma unroll
            for (int nt = 0; nt < 4; nt++) {
                const int n = nh * 32 + nt * 8 + ln4;
                uint32_t bh[2] = {Bh[n][ci], Bh[n][ci + 4]};
                uint32_t bl[2] = {Bl[n][ci], Bl[n][ci + 4]};
                mma16(c[nt], ah, bh);
                mma16(c[nt], ah, bl);
                mma16(c[nt], al, bh);
            }
        }
        __syncthreads();
    }

    const int row0 = r0 + arow;
#pragma unroll
    for (int nt = 0; nt < 4; nt++) {
        const int col = nh * 32 + nt * 8 + 2 * kp;
        float b0 = bias[col], b1 = bias[col + 1];
        float2 o0 = {(c[nt][0] + b0) * scale, (c[nt][1] + b1) * scale};
        float2 o1 = {(c[nt][2] + b0) * scale, (c[nt][3] + b1) * scale};
        *(float2*)&out[row0 * DK + col]       = o0;
        *(float2*)&out[(row0 + 8) * DK + col] = o1;
    }
}

// ---------------------------------------------------------------------------
// Flash attention, split-KV, bf16 split MMA, register-resident softmax.
// q-tile 64, k-tile 64, 256 threads. Warp (mt = w&3, nh = w>>2):
//   QK: computes S cols nh*32..+31 for rows mt*16..+15.
//   PV: accumulates over its OWN 32 kcols into full 64-wide O partial;
//       the two nh partials merge once at the end via smem.
// ---------------------------------------------------------------------------
struct ASmem {
    uint32_t Qh[64][36], Ql[64][36];   // [qrow][dpair]
    uint32_t Kh[64][36], Kl[64][36];   // [kcol][dpair]
    uint32_t Vh[32][72], Vl[32][72];   // [kcolpair][v]
    float Ob[64][66];                  // O merge buffer
    float m_s[64], l_s[64];
    float pm[128], ps[128];
};

__global__ __launch_bounds__(256, 2)
void attn_kernel()
{
    extern __shared__ char raw[];
    ASmem& S = *reinterpret_cast<ASmem*>(raw);

    const int t    = threadIdx.x;
    const int w    = t >> 5;
    const int lane = t & 31;
    const int kp   = lane & 3;
    const int ln4  = lane >> 2;
    const int mt   = w & 3, nh = w >> 2;
    const int q0   = blockIdx.x * 64;
    const int b    = blockIdx.y;
    const int z    = blockIdx.z;
    const int base = b * SEQ;
    const float NEG_INF = __int_as_float(0xff800000u);
    const int qr = mt * 16 + ln4;

    // stage Q (split+pack): 1024 float4, 4/thread
#pragma unroll
    for (int i = 0; i < 4; i++) {
        int f = i * 256 + t, row = f >> 4, d4 = (f & 15) * 4;
        float4 qv = *(const float4*)&g_Q[(base + q0 + row) * DK + d4];
        uint32_t h0, l0, h1, l1;
        split_pair(qv.x, qv.y, h0, l0);
        split_pair(qv.z, qv.w, h1, l1);
        *(uint2*)&S.Qh[row][d4 >> 1] = make_uint2(h0, h1);
        *(uint2*)&S.Ql[row][d4 >> 1] = make_uint2(l0, l1);
    }
    if (t < 64) { S.m_s[t] = NEG_INF; S.l_s[t] = 0.f; }

    float o[8][4];
#pragma unroll
    for (int i = 0; i < 8; i++)
#pragma unroll
        for (int j = 0; j < 4; j++) o[i][j] = 0.f;

    for (int k0 = z * KPS; k0 < (z + 1) * KPS; k0 += 64) {
        __syncthreads();
        // stage K: [kcol][dpair]
#pragma unroll
        for (int i = 0; i < 4; i++) {
            int f = i * 256 + t, row = f >> 4, d4 = (f & 15) * 4;
            float4 kv = *(const float4*)&g_K[(base + k0 + row) * DK + d4];
            uint32_t h0, l0, h1, l1;
            split_pair(kv.x, kv.y, h0, l0);
            split_pair(kv.z, kv.w, h1, l1);
            *(uint2*)&S.Kh[row][d4 >> 1] = make_uint2(h0, h1);
            *(uint2*)&S.Kl[row][d4 >> 1] = make_uint2(l0, l1);
        }
        // stage V transposed-packed: [kcolpair][v], 512 tasks, 2/thread
#pragma unroll
        for (int i = 0; i < 2; i++) {
            int f = i * 256 + t, cp = f >> 4, d4 = (f & 15) * 4;
            const float* vp = &g_V[(base + k0 + 2 * cp) * DK + d4];
            float4 v0 = *(const float4*)vp;
            float4 v1 = *(const float4*)(vp + DK);
            uint4 hh, ll;
            split_pair(v0.x, v1.x, hh.x, ll.x);
            split_pair(v0.y, v1.y, hh.y, ll.y);
            split_pair(v0.z, v1.z, hh.z, ll.z);
            split_pair(v0.w, v1.w, hh.w, ll.w);
            *(uint4*)&S.Vh[cp][d4] = hh;
            *(uint4*)&S.Vl[cp][d4] = ll;
        }
        __syncthreads();

        // ---- S = Q K^T ----
        float s[4][4];
#pragma unroll
        for (int i = 0; i < 4; i++)
#pragma unroll
            for (int j = 0; j < 4; j++) s[i][j] = 0.f;

#pragma unroll
        for (int ks = 0; ks < 4; ks++) {
            const int ci = ks * 8 + kp;
            uint32_t ah[4] = {S.Qh[qr][ci], S.Qh[qr + 8][ci],
                              S.Qh[qr][ci + 4], S.Qh[qr + 8][ci + 4]};
            uint32_t al[4] = {S.Ql[qr][ci], S.Ql[qr + 8][ci],
                              S.Ql[qr][ci + 4], S.Ql[qr + 8][ci + 4]};
#pragma unroll
            for (int nt = 0; nt < 4; nt++) {
                const int n = nh * 32 + nt * 8 + ln4;
                uint32_t bh[2] = {S.Kh[n][ci], S.Kh[n][ci + 4]};
                uint32_t bl[2] = {S.Kl[n][ci], S.Kl[n][ci + 4]};
                mma16(s[nt], ah, bh);
                mma16(s[nt], ah, bl);
                mma16(s[nt], al, bh);
            }
        }

        // ---- softmax (register + shuffle) ----
        float mx0 = NEG_INF, mx1 = NEG_INF;
#pragma unroll
        for (int nt = 0; nt < 4; nt++) {
            mx0 = fmaxf(mx0, fmaxf(s[nt][0], s[nt][1]));
            mx1 = fmaxf(mx1, fmaxf(s[nt][2], s[nt][3]));
        }
        mx0 = fmaxf(mx0, __shfl_xor_sync(0xffffffffu, mx0, 1));
        mx0 = fmaxf(mx0, __shfl_xor_sync(0xffffffffu, mx0, 2));
        mx1 = fmaxf(mx1, __shfl_xor_sync(0xffffffffu, mx1, 1));
        mx1 = fmaxf(mx1, __shfl_xor_sync(0xffffffffu, mx1, 2));
        if (kp == 0) {
            S.pm[2 * qr + nh]       = mx0;
            S.pm[2 * (qr + 8) + nh] = mx1;
        }
        __syncthreads();

        float mo0 = S.m_s[qr], mo1 = S.m_s[qr + 8];
        float mn0 = fmaxf(mo0, fmaxf(S.pm[2 * qr], S.pm[2 * qr + 1]));
        float mn1 = fmaxf(mo1, fmaxf(S.pm[2 * (qr + 8)], S.pm[2 * (qr + 8) + 1]));
        float f0 = fexp(mo0 - mn0), f1 = fexp(mo1 - mn1);

        float s0 = 0.f, s1 = 0.f;
#pragma unroll
        for (int nt = 0; nt < 4; nt++) {
            s[nt][0] = fexp(s[nt][0] - mn0);
            s[nt][1] = fexp(s[nt][1] - mn0);
            s[nt][2] = fexp(s[nt][2] - mn1);
            s[nt][3] = fexp(s[nt][3] - mn1);
            s0 += s[nt][0] + s[nt][1];
            s1 += s[nt][2] + s[nt][3];
        }
        s0 += __shfl_xor_sync(0xffffffffu, s0, 1);
        s0 += __shfl_xor_sync(0xffffffffu, s0, 2);
        s1 += __shfl_xor_sync(0xffffffffu, s1, 1);
        s1 += __shfl_xor_sync(0xffffffffu, s1, 2);
        if (kp == 0) {
            S.ps[2 * qr + nh]       = s0;
            S.ps[2 * (qr + 8) + nh] = s1;
        }
        __syncthreads();
        if (nh == 0 && kp == 0) {
            S.l_s[qr]     = S.l_s[qr] * f0 + S.ps[2 * qr] + S.ps[2 * qr + 1];
            S.m_s[qr]     = mn0;
            S.l_s[qr + 8] = S.l_s[qr + 8] * f1 +
                            S.ps[2 * (qr + 8)] + S.ps[2 * (qr + 8) + 1];
            S.m_s[qr + 8] = mn1;
        }

        // ---- rescale O, accumulate P·V over this warp's 32 kcols ----
#pragma unroll
        for (int j = 0; j < 8; j++) {
            o[j][0] *= f0; o[j][1] *= f0;
            o[j][2] *= f1; o[j][3] *= f1;
        }
#pragma unroll
        for (int s01 = 0; s01 < 2; s01++) {
            const int ks = 2 * nh + s01;
            uint32_t ph[4], pl[4];
            split_pair(s[2 * s01][0],     s[2 * s01][1],     ph[0], pl[0]);
            split_pair(s[2 * s01][2],     s[2 * s01][3],     ph[1], pl[1]);
            split_pair(s[2 * s01 + 1][0], s[2 * s01 + 1][1], ph[2], pl[2]);
            split_pair(s[2 * s01 + 1][2], s[2 * s01 + 1][3], ph[3], pl[3]);
#pragma unroll
            for (int nt8 = 0; nt8 < 8; nt8++) {
                const int n = nt8 * 8 + ln4;
                uint32_t vh[2] = {S.Vh[ks * 8 + kp][n], S.Vh[ks * 8 + kp + 4][n]};
                uint32_t vl[2] = {S.Vl[ks * 8 + kp][n], S.Vl[ks * 8 + kp + 4][n]};
                mma16(o[nt8], ph, vh);
                mma16(o[nt8], ph, vl);
                mma16(o[nt8], pl, vh);
            }
        }
    }

    // ---- merge nh partials, normalize, write ----
    if (nh == 1) {
#pragma unroll
        for (int nt8 = 0; nt8 < 8; nt8++) {
            const int col = nt8 * 8 + 2 * kp;
            *(float2*)&S.Ob[qr][col]     = make_float2(o[nt8][0], o[nt8][1]);
            *(float2*)&S.Ob[qr + 8][col] = make_float2(o[nt8][2], o[nt8][3]);
        }
    }
    __syncthreads();
    if (nh == 0) {
        float inv0 = 1.0f / S.l_s[qr];
        float inv1 = 1.0f / S.l_s[qr + 8];
        const int gr = base + q0 + qr;
#pragma unroll
        for (int nt8 = 0; nt8 < 8; nt8++) {
            const int col = nt8 * 8 + 2 * kp;
            float2 a0 = *(float2*)&S.Ob[qr][col];
            float2 a1 = *(float2*)&S.Ob[qr + 8][col];
            float2 r0v = {(o[nt8][0] + a0.x) * inv0, (o[nt8][1] + a0.y) * inv0};
            float2 r1v = {(o[nt8][2] + a1.x) * inv1, (o[nt8][3] + a1.y) * inv1};
            *(float2*)&g_Op[(z * BSR + gr) * DK + col]     = r0v;
            *(float2*)&g_Op[(z * BSR + gr + 8) * DK + col] = r1v;
        }
    }
    if (t < 64) {
        int gr = base + q0 + t;
        g_m[z * BSR + gr] = S.m_s[t];
        g_l[z * BSR + gr] = S.l_s[t];
    }
}

// ---------------------------------------------------------------------------
// Combine: merge NSPL split partials per row (partials normalized per split).
// ---------------------------------------------------------------------------
__global__ __launch_bounds__(256)
void combine_kernel(float* __restrict__ out)
{
    int gid = blockIdx.x * 256 + threadIdx.x;
    int row = gid >> 4;
    int c4  = (gid & 15) * 4;

    float m[NSPL], ww[NSPL];
#pragma unroll
    for (int i = 0; i < NSPL; i++) m[i] = g_m[i * BSR + row];
    float M = fmaxf(fmaxf(m[0], m[1]), fmaxf(m[2], m[3]));

    float denom = 0.f;
#pragma unroll
    for (int i = 0; i < NSPL; i++) {
        ww[i] = fexp(m[i] - M);
        denom += ww[i] * g_l[i * BSR + row];
    }
    float inv = 1.0f / denom;

    float4 acc = {0.f, 0.f, 0.f, 0.f};
#pragma unroll
    for (int i = 0; i < NSPL; i++) {
        float wl = ww[i] * g_l[i * BSR + row];
        float4 ov = *(const float4*)&g_Op[(i * BSR + row) * DK + c4];
        acc.x += wl * ov.x; acc.y += wl * ov.y;
        acc.z += wl * ov.z; acc.w += wl * ov.w;
    }
    float4 r = {acc.x * inv, acc.y * inv, acc.z * inv, acc.w * inv};
    *(float4*)&out[row * DK + c4] = r;
}

// ---------------------------------------------------------------------------
extern "C" void kernel_launch(void* const* d_in, const int* in_sizes, int n_in,
                              void* d_out, int out_size)
{
    const float* q  = (const float*)d_in[0];
    const float* k  = (const float*)d_in[1];
    const float* v  = (const float*)d_in[2];
    const float* Wq = (const float*)d_in[3];
    const float* bq = (const float*)d_in[4];
    const float* Wk = (const float*)d_in[5];
    const float* bk = (const float*)d_in[6];
    const float* Wv = (const float*)d_in[7];
    const float* bv = (const float*)d_in[8];
    float* out = (float*)d_out;

    cudaFuncSetAttribute(attn_kernel, cudaFuncAttributeMaxDynamicSharedMemorySize,
                         (int)sizeof(ASmem));

    w_prep<<<dim3(DM / 64, 3), 256>>>(Wq, Wk, Wv);
    proj_mma<<<dim3(BSR / 64, 3), 256>>>(q, k, v, bq, bk, bv);
    attn_kernel<<<dim3(SEQ / 64, NB, NSPL), 256, sizeof(ASmem)>>>();
    combine_kernel<<<(BSR * 16) / 256, 256>>>(out);
}